// round 15
// baseline (speedup 1.0000x reference)
#include <cuda_runtime.h>
#include <cuda_fp16.h>
#include <cstdint>
#include <math.h>

#define SEQ 512
#define NB  64
#define NH  1024
#define NG  4096

// ---------------- scratch (static device globals: allocation-free) ----------------
__device__ __half g_xh [SEQ * NB * NH];  // x in fp16 (64 MB)
__device__ __half g_wih[NG * NH];        // weights fp16 (8 MB each)
__device__ __half g_whh[NG * NH];
__device__ float  g_bias[NG];            // bias_ih + bias_hh (f32)
__device__ float  g_g0 [(size_t)SEQ * NB * NG];   // precomputed X @ W_ih^T (537 MB)
__device__ __half g_h0[2][NB * NH];      // double-buffered layer0 h (fp16)
__device__ __half g_h1[2][NB * NH];
__device__ unsigned g_cnt;               // grid barrier arrival counter
__device__ volatile unsigned g_gen;      // grid barrier generation

__global__ void k_cvt(const float* __restrict__ src, int which, int n4) {
    __half* dst = (which == 0) ? g_xh : (which == 1 ? g_wih : g_whh);
    for (int i = blockIdx.x * blockDim.x + threadIdx.x; i < n4; i += gridDim.x * blockDim.x) {
        float4 v = ((const float4*)src)[i];
        ((__half2*)dst)[2 * i]     = __floats2half2_rn(v.x, v.y);
        ((__half2*)dst)[2 * i + 1] = __floats2half2_rn(v.z, v.w);
    }
}
__global__ void k_bias(const float* __restrict__ a, const float* __restrict__ b) {
    for (int i = blockIdx.x * blockDim.x + threadIdx.x; i < NG; i += gridDim.x * blockDim.x)
        g_bias[i] = a[i] + b[i];
}
__global__ void k_init() {
    int i0 = blockIdx.x * blockDim.x + threadIdx.x;
    if (i0 == 0) { g_cnt = 0u; g_gen = 0u; }
    const __half z = __float2half(0.f);
    for (int i = i0; i < NB * NH; i += gridDim.x * blockDim.x) {
        g_h0[0][i] = z; g_h0[1][i] = z;
        g_h1[0][i] = z; g_h1[1][i] = z;
    }
}

// ---------------- PTX helpers ----------------
__device__ __forceinline__ void cp16(uint32_t dst, const void* src) {
    asm volatile("cp.async.cg.shared.global [%0], [%1], 16;\n" :: "r"(dst), "l"(src));
}
#define CP_COMMIT() asm volatile("cp.async.commit_group;\n" ::: "memory")
#define CP_WAIT(N)  asm volatile("cp.async.wait_group %0;\n" :: "n"(N) : "memory")
__device__ __forceinline__ uint32_t smem_u32(const void* p) {
    uint32_t r;
    asm("{ .reg .u64 t; cvta.to.shared.u64 t, %1; cvt.u32.u64 %0, t; }" : "=r"(r) : "l"(p));
    return r;
}
__device__ __forceinline__ void ldsm4(uint32_t& r0, uint32_t& r1, uint32_t& r2, uint32_t& r3,
                                      uint32_t addr) {
    asm volatile("ldmatrix.sync.aligned.m8n8.x4.shared.b16 {%0,%1,%2,%3}, [%4];"
                 : "=r"(r0), "=r"(r1), "=r"(r2), "=r"(r3) : "r"(addr));
}
__device__ __forceinline__ void mma16816(float* a4, const uint32_t* af, uint32_t b0, uint32_t b1) {
    asm volatile(
        "mma.sync.aligned.m16n8k16.row.col.f32.f16.f16.f32 "
        "{%0,%1,%2,%3}, {%4,%5,%6,%7}, {%8,%9}, {%0,%1,%2,%3};\n"
        : "+f"(a4[0]), "+f"(a4[1]), "+f"(a4[2]), "+f"(a4[3])
        : "r"(af[0]), "r"(af[1]), "r"(af[2]), "r"(af[3]), "r"(b0), "r"(b1));
}
__device__ __forceinline__ float fsig(float x) { return 1.f / (1.f + __expf(-x)); }
__device__ __forceinline__ float ftanh(float x) { return 1.f - 2.f / (1.f + __expf(2.f * x)); }

// =============== k_pre: G0 = X[32768,1024] @ W_ih[4096,1024]^T (f32 out) ===========
#define P_STAGE (256 * 144)                  // A 128 rows + B 128 rows, 144B rows
#define P_SMEM  (3 * P_STAGE)                // 110592
__global__ __launch_bounds__(256) void k_pre() {
    extern __shared__ char ps[];
    const uint32_t s0 = smem_u32(ps);
    const int tid = threadIdx.x, lane = tid & 31, wid = tid >> 5;
    const int wr = (wid >> 1) * 32, wc = (wid & 1) * 64;
    const int row0 = blockIdx.y * 128, col0 = blockIdx.x * 128;
    const int g = lane >> 2, t = lane & 3, lrow = lane & 15, lhiw = (lane >> 4) * 4;
    const int bn_row = ((lane >> 4) << 3) + (lane & 7), bn_wof = ((lane >> 3) & 1) * 4;

    auto issue = [&](int ch, int st) {
        const uint32_t aU = s0 + (uint32_t)st * P_STAGE, bU = aU + 128 * 144;
        const int kb = ch * 64;
        #pragma unroll
        for (int i = 0; i < 4; i++) {
            int id = i * 256 + tid; int m = id >> 3, q = id & 7;
            cp16(aU + (uint32_t)(m * 144 + q * 16),
                 g_xh + (size_t)(row0 + m) * NH + kb + q * 8);
        }
        #pragma unroll
        for (int i = 0; i < 4; i++) {
            int id = i * 256 + tid; int m = id >> 3, q = id & 7;
            cp16(bU + (uint32_t)(m * 144 + q * 16),
                 g_wih + (size_t)(col0 + m) * NH + kb + q * 8);
        }
        CP_COMMIT();
    };

    float acc[2][8][4];
    #pragma unroll
    for (int a = 0; a < 2; a++)
        #pragma unroll
        for (int b = 0; b < 8; b++)
            #pragma unroll
            for (int c = 0; c < 4; c++) acc[a][b][c] = 0.f;

    issue(0, 0); issue(1, 1);
    for (int c = 0; c < 16; ++c) {
        if (c < 15) { CP_WAIT(1); } else { CP_WAIT(0); }
        __syncthreads();
        if (c + 2 < 16) issue(c + 2, (c + 2) % 3);
        const uint32_t aU = s0 + (uint32_t)(c % 3) * P_STAGE, bU = aU + 128 * 144;
        #pragma unroll
        for (int ks = 0; ks < 4; ks++) {
            const int ko = ks * 8;
            uint32_t afr[2][4], bfr[4][4];
            #pragma unroll
            for (int mi = 0; mi < 2; mi++)
                ldsm4(afr[mi][0], afr[mi][1], afr[mi][2], afr[mi][3],
                      aU + (uint32_t)(((wr + mi * 16 + lrow) * 36 + ko + lhiw) * 4));
            #pragma unroll
            for (int nb = 0; nb < 4; nb++)
                ldsm4(bfr[nb][0], bfr[nb][1], bfr[nb][2], bfr[nb][3],
                      bU + (uint32_t)(((wc + nb * 16 + bn_row) * 36 + ko + bn_wof) * 4));
            #pragma unroll
            for (int mi = 0; mi < 2; mi++)
                #pragma unroll
                for (int n8 = 0; n8 < 8; n8++)
                    mma16816(acc[mi][n8], afr[mi],
                             bfr[n8 >> 1][2 * (n8 & 1)], bfr[n8 >> 1][2 * (n8 & 1) + 1]);
        }
        __syncthreads();
    }
    #pragma unroll
    for (int mi = 0; mi < 2; mi++) {
        int r0 = row0 + wr + mi * 16 + g;
        #pragma unroll
        for (int n8 = 0; n8 < 8; n8++) {
            int col = col0 + wc + n8 * 8 + 2 * t;
            *(float2*)&g_g0[(size_t)r0 * NG + col]       = make_float2(acc[mi][n8][0], acc[mi][n8][1]);
            *(float2*)&g_g0[(size_t)(r0 + 8) * NG + col] = make_float2(acc[mi][n8][2], acc[mi][n8][3]);
        }
    }
}

// =============== recurrent kernel ==================================================
// SMEM: A ring 4 stages x [h0 64x144B | h1 64x144B] + resident B 32 chunks.
// R15: 4-stage ring, ONE sync per 2 chunks (8 mainloop barriers instead of 16).
// Iteration i: consumers read slots {2i,2i+1}%4, producers write {2i+2,2i+3}%4
// (disjoint); producer CP_WAIT(0) before the sync makes readiness exact.
#define A_ROWB    144
#define R_STAGE   (128 * A_ROWB)             // 18432 (h0 half + h1 half)
#define B_OFF     (4 * R_STAGE)              // 73728
#define B_CHUNK_B (32 * A_ROWB)              // 4608
#define SMEM_TOT  (B_OFF + 32 * B_CHUNK_B)   // 221184
#define NT 512

// 12 consumer warps: cg = wid>>2 (0: L0+=h0*Whh | 1: L1+=h0*Wih | 2: L1+=h1*Whh),
// band = wid&3 (16-row band), warp tile 16x32. 4 producer warps (12-15) do all
// cp.async. G0 added in epilogue from registers (prefetched a slot early).
__global__ __launch_bounds__(NT) void k_lstm(float* __restrict__ out, int wstates) {
    extern __shared__ char dyn[];

    const int tid  = threadIdx.x;
    const int lane = tid & 31;
    const int wid  = tid >> 5;
    const int j0   = blockIdx.x * 8;

    const uint32_t smem0 = smem_u32(dyn);
    const uint32_t bRes  = smem0 + B_OFF;

    // ---- resident B (once): chunk-major, 16 Wih chunks then 16 Whh chunks ----
    {
        if (tid < 256) {
            const int n = tid >> 3, q = tid & 7;
            const int grow = (n >> 3) * NH + j0 + (n & 7);
            for (int c = 0; c < 32; c++) {
                const __half* wb = (c < 16) ? g_wih : g_whh;
                const int kk = (c * 64) & (NH - 1);
                cp16(bRes + (uint32_t)(c * B_CHUNK_B + n * A_ROWB + q * 16),
                     wb + (size_t)grow * NH + kk + q * 8);
                CP_COMMIT();
            }
        }
        CP_WAIT(0);
        __syncthreads();
    }

    const int g = lane >> 2, t = lane & 3;
    const int lrow = lane & 15, lhiw = (lane >> 4) * 4;
    const int bn_row = ((lane >> 4) << 3) + (lane & 7);
    const int bn_wof = ((lane >> 3) & 1) * 4;
    const uint32_t bFragBase = bRes + (uint32_t)((bn_row * 36 + bn_wof) * 4);

    const bool isCons = (wid < 12);
    const int  cg     = wid >> 2;          // 0..2 (consumers)
    const int  band   = wid & 3;
    const int  ptid   = tid & 127;         // producer lane-id within 4 warps

    // ---- persistent per-thread epilogue state ----
    const int erow  = tid >> 2;            // 0..127
    const int ehalf = erow >> 6;
    const int eb    = erow & 63;
    const int ejb   = (tid & 3) * 2;
    float cv[2] = {0.f, 0.f};
    float bias_r[4][2];
    #pragma unroll
    for (int q = 0; q < 4; q++)
        #pragma unroll
        for (int u = 0; u < 2; u++)
            bias_r[q][u] = g_bias[q * NH + j0 + ejb + u];

    float2 rg0[4];
    auto fetch_g0 = [&](int tt) {
        if (ehalf == 0) {
            const size_t base = ((size_t)tt * NB + eb) * NG + j0 + ejb;
            #pragma unroll
            for (int q = 0; q < 4; q++) rg0[q] = *(const float2*)&g_g0[base + q * NH];
        }
    };
    fetch_g0(0);

    for (int s = 0; s <= SEQ; ++s) {
        const int rp = s & 1, wq = rp ^ 1;
        const __half* h0r = g_h0[rp];
        const __half* h1r = g_h1[rp];
        __half* h0w = g_h0[wq];
        __half* h1w = g_h1[wq];
        const bool doL0 = (s < SEQ);
        const bool doL1 = (s > 0);
        const int  t1   = s - 1;

        // ---- producer chunk loader: chunk j -> stage slot ----
        auto issue_chunk = [&](int j, int slot) {
            const uint32_t st = smem0 + (uint32_t)slot * R_STAGE;
            const int kb = j * 64;
            #pragma unroll
            for (int i = 0; i < 4; i++) {
                int id = i * 128 + ptid; int m = id >> 3, q = id & 7;
                cp16(st + (uint32_t)(m * A_ROWB + q * 16), h0r + m * NH + kb + q * 8);
            }
            #pragma unroll
            for (int i = 0; i < 4; i++) {
                int id = i * 128 + ptid; int m = id >> 3, q = id & 7;
                cp16(st + (uint32_t)(9216 + m * A_ROWB + q * 16), h1r + m * NH + kb + q * 8);
            }
            CP_COMMIT();
        };

        float acc[4][4];
        #pragma unroll
        for (int b = 0; b < 4; b++)
            #pragma unroll
            for (int c = 0; c < 4; c++) acc[b][c] = 0.f;

        // prologue: first iteration's 2 chunks
        if (!isCons) { issue_chunk(0, 0); issue_chunk(1, 1); }

        for (int i = 0; i < 8; ++i) {
            if (!isCons) CP_WAIT(0);      // chunks 2i, 2i+1 fully landed
            __syncthreads();              // also: slots {2i+2,2i+3}%4 free (prev iter done)
            if (!isCons) {
                if (i < 7) {
                    issue_chunk(2 * i + 2, (2 * i + 2) & 3);
                    issue_chunk(2 * i + 3, (2 * i + 3) & 3);
                }
            } else {
                #pragma unroll
                for (int cc = 0; cc < 2; cc++) {
                    const int c = 2 * i + cc;
                    const uint32_t aBase = smem0 + (uint32_t)(c & 3) * R_STAGE
                                         + (cg == 2 ? 9216u : 0u);
                    const uint32_t bC = bFragBase
                                      + (uint32_t)(((cg == 1) ? c : 16 + c) * B_CHUNK_B);
                    #pragma unroll
                    for (int ks = 0; ks < 4; ks++) {
                        const int ko = ks * 8;
                        uint32_t afr[4], b0[4], b1[4];
                        ldsm4(afr[0], afr[1], afr[2], afr[3],
                              aBase + (uint32_t)(((band * 16 + lrow) * 36 + ko + lhiw) * 4));
                        ldsm4(b0[0], b0[1], b0[2], b0[3], bC + (uint32_t)(ko * 4));
                        ldsm4(b1[0], b1[1], b1[2], b1[3], bC + (uint32_t)(16 * 144 + ko * 4));
                        mma16816(acc[0], afr, b0[0], b0[1]);
                        mma16816(acc[1], afr, b0[2], b0[3]);
                        mma16816(acc[2], afr, b1[0], b1[1]);
                        mma16816(acc[3], afr, b1[2], b1[3]);
                    }
                }
            }
        }

        __syncthreads();                  // mainloop done; ring free for sG

        // ------- gate exchange: sG0 [128][36] (rows 0-63 gemm0, 64-127 gemm1),
        //         sG2 [64][36] (gemm2, added to rows 64-127) -------
        float* sG0 = (float*)dyn;
        float* sG2 = (float*)(dyn + 18432);
        if (isCons) {
            float* dst = (cg == 0) ? sG0 : (cg == 1 ? sG0 + 64 * 36 : sG2);
            const int r = band * 16 + g;
            #pragma unroll
            for (int ni = 0; ni < 4; ni++) {
                int cc = ni * 8 + 2 * t;
                dst[r * 36 + cc]           = acc[ni][0];
                dst[r * 36 + cc + 1]       = acc[ni][1];
                dst[(r + 8) * 36 + cc]     = acc[ni][2];
                dst[(r + 8) * 36 + cc + 1] = acc[ni][3];
            }
        }
        __syncthreads();

        {
            const bool act = (ehalf == 0) ? doL0 : doL1;
            if (act) {
                __half* hwb = ehalf ? h1w : h0w;
                const int idx = eb * NH + j0 + ejb;
                float hv[2];
                #pragma unroll
                for (int u = 0; u < 2; u++) {
                    int uu = ejb + u;
                    float gq[4];
                    #pragma unroll
                    for (int q = 0; q < 4; q++) {
                        gq[q] = sG0[erow * 36 + q * 8 + uu] + bias_r[q][u];
                        if (ehalf == 0) gq[q] += (u == 0 ? rg0[q].x : rg0[q].y);
                        else            gq[q] += sG2[(erow - 64) * 36 + q * 8 + uu];
                    }
                    float cn = fsig(gq[1]) * cv[u] + fsig(gq[0]) * ftanh(gq[2]);
                    cv[u] = cn;
                    hv[u] = fsig(gq[3]) * ftanh(cn);
                }
                *(__half2*)&hwb[idx] = __floats2half2_rn(hv[0], hv[1]);
                if (ehalf == 1) {
                    *(float2*)&out[((size_t)t1 * NB + eb) * NH + j0 + ejb] =
                        make_float2(hv[0], hv[1]);
                    if (wstates && t1 == SEQ - 1) {
                        #pragma unroll
                        for (int u = 0; u < 2; u++) {
                            out[(size_t)SEQ * NB * NH + NB * NH + idx + u]     = hv[u];
                            out[(size_t)SEQ * NB * NH + 3 * NB * NH + idx + u] = cv[u];
                        }
                    }
                } else if (wstates && s == SEQ - 1) {
                    #pragma unroll
                    for (int u = 0; u < 2; u++) {
                        out[(size_t)SEQ * NB * NH + idx + u]               = hv[u];
                        out[(size_t)SEQ * NB * NH + 2 * NB * NH + idx + u] = cv[u];
                    }
                }
            }
        }

        // ---- prefetch next slot's G0 into registers (overlaps barrier) ----
        if (s < SEQ) fetch_g0((s + 1 < SEQ) ? (s + 1) : (SEQ - 1));

        // ------- grid barrier (sense counter) -------
        if (s < SEQ) {
            __syncthreads();
            if (tid == 0) {
                __threadfence();
                unsigned a = atomicAdd(&g_cnt, 1u);
                unsigned target = (unsigned)(s + 1);
                if (a == 127u) {
                    g_cnt = 0u;
                    __threadfence();
                    g_gen = target;
                } else {
                    while (g_gen < target) { }
                    __threadfence();
                }
            }
            __syncthreads();
        }
    }
}

// ---------------------------------------------------------------------------------
extern "C" void kernel_launch(void* const* d_in, const int* in_sizes, int n_in,
                              void* d_out, int out_size) {
    const float* x   = (const float*)d_in[0];
    const float* wih = (const float*)d_in[1];
    const float* whh = (const float*)d_in[2];
    const float* bih = (const float*)d_in[3];
    const float* bhh = (const float*)d_in[4];
    float* out = (float*)d_out;

    const long long full = (long long)SEQ * NB * NH + 4LL * NB * NH;
    int wstates = ((long long)out_size >= full) ? 1 : 0;

    static int smem_set = 0;
    if (!smem_set) {
        cudaFuncSetAttribute(k_lstm, cudaFuncAttributeMaxDynamicSharedMemorySize, SMEM_TOT);
        cudaFuncSetAttribute(k_pre,  cudaFuncAttributeMaxDynamicSharedMemorySize, P_SMEM);
        smem_set = 1;
    }

    k_cvt<<<512, 256>>>(x, 0, SEQ * NB * NH / 4);
    k_cvt<<<256, 256>>>(wih, 1, NG * NH / 4);
    k_cvt<<<256, 256>>>(whh, 2, NG * NH / 4);
    k_bias<<<16, 256>>>(bih, bhh);
    k_init<<<128, 256>>>();

    k_pre<<<dim3(NG / 128, SEQ * NB / 128), 256, P_SMEM>>>();

    k_lstm<<<128, NT, SMEM_TOT>>>(out, wstates);
}

// round 16
// speedup vs baseline: 1.1001x; 1.1001x over previous
#include <cuda_runtime.h>
#include <cuda_fp16.h>
#include <cstdint>
#include <math.h>

#define SEQ 512
#define NB  64
#define NH  1024
#define NG  4096

// ---------------- scratch (static device globals: allocation-free) ----------------
__device__ __half g_xh [SEQ * NB * NH];  // x in fp16 (64 MB)
__device__ __half g_wih[NG * NH];        // weights fp16 (8 MB each)
__device__ __half g_whh[NG * NH];
__device__ float  g_bias[NG];            // bias_ih + bias_hh (f32)
__device__ float  g_g0 [(size_t)SEQ * NB * NG];   // precomputed X @ W_ih^T (537 MB)
__device__ __half g_h0[2][NB * NH];      // double-buffered layer0 h (fp16)
__device__ __half g_h1[2][NB * NH];
__device__ unsigned g_cnt;               // grid barrier arrival counter
__device__ volatile unsigned g_gen;      // grid barrier generation

__global__ void k_cvt(const float* __restrict__ src, int which, int n4) {
    __half* dst = (which == 0) ? g_xh : (which == 1 ? g_wih : g_whh);
    for (int i = blockIdx.x * blockDim.x + threadIdx.x; i < n4; i += gridDim.x * blockDim.x) {
        float4 v = ((const float4*)src)[i];
        ((__half2*)dst)[2 * i]     = __floats2half2_rn(v.x, v.y);
        ((__half2*)dst)[2 * i + 1] = __floats2half2_rn(v.z, v.w);
    }
}
__global__ void k_bias(const float* __restrict__ a, const float* __restrict__ b) {
    for (int i = blockIdx.x * blockDim.x + threadIdx.x; i < NG; i += gridDim.x * blockDim.x)
        g_bias[i] = a[i] + b[i];
}
__global__ void k_init() {
    int i0 = blockIdx.x * blockDim.x + threadIdx.x;
    if (i0 == 0) { g_cnt = 0u; g_gen = 0u; }
    const __half z = __float2half(0.f);
    for (int i = i0; i < NB * NH; i += gridDim.x * blockDim.x) {
        g_h0[0][i] = z; g_h0[1][i] = z;
        g_h1[0][i] = z; g_h1[1][i] = z;
    }
}

// ---------------- PTX helpers ----------------
__device__ __forceinline__ void cp16(uint32_t dst, const void* src) {
    asm volatile("cp.async.cg.shared.global [%0], [%1], 16;\n" :: "r"(dst), "l"(src));
}
#define CP_COMMIT() asm volatile("cp.async.commit_group;\n" ::: "memory")
#define CP_WAIT(N)  asm volatile("cp.async.wait_group %0;\n" :: "n"(N) : "memory")
__device__ __forceinline__ uint32_t smem_u32(const void* p) {
    uint32_t r;
    asm("{ .reg .u64 t; cvta.to.shared.u64 t, %1; cvt.u32.u64 %0, t; }" : "=r"(r) : "l"(p));
    return r;
}
__device__ __forceinline__ void ldsm4(uint32_t& r0, uint32_t& r1, uint32_t& r2, uint32_t& r3,
                                      uint32_t addr) {
    asm volatile("ldmatrix.sync.aligned.m8n8.x4.shared.b16 {%0,%1,%2,%3}, [%4];"
                 : "=r"(r0), "=r"(r1), "=r"(r2), "=r"(r3) : "r"(addr));
}
__device__ __forceinline__ void mma16816(float* a4, const uint32_t* af, uint32_t b0, uint32_t b1) {
    asm volatile(
        "mma.sync.aligned.m16n8k16.row.col.f32.f16.f16.f32 "
        "{%0,%1,%2,%3}, {%4,%5,%6,%7}, {%8,%9}, {%0,%1,%2,%3};\n"
        : "+f"(a4[0]), "+f"(a4[1]), "+f"(a4[2]), "+f"(a4[3])
        : "r"(af[0]), "r"(af[1]), "r"(af[2]), "r"(af[3]), "r"(b0), "r"(b1));
}
__device__ __forceinline__ float fsig(float x) { return 1.f / (1.f + __expf(-x)); }
__device__ __forceinline__ float ftanh(float x) { return 1.f - 2.f / (1.f + __expf(2.f * x)); }

// =============== k_pre: G0 = X[32768,1024] @ W_ih[4096,1024]^T (f32 out) ===========
#define P_STAGE (256 * 144)                  // A 128 rows + B 128 rows, 144B rows
#define P_SMEM  (3 * P_STAGE)                // 110592
__global__ __launch_bounds__(256) void k_pre() {
    extern __shared__ char ps[];
    const uint32_t s0 = smem_u32(ps);
    const int tid = threadIdx.x, lane = tid & 31, wid = tid >> 5;
    const int wr = (wid >> 1) * 32, wc = (wid & 1) * 64;
    const int row0 = blockIdx.y * 128, col0 = blockIdx.x * 128;
    const int g = lane >> 2, t = lane & 3, lrow = lane & 15, lhiw = (lane >> 4) * 4;
    const int bn_row = ((lane >> 4) << 3) + (lane & 7), bn_wof = ((lane >> 3) & 1) * 4;

    auto issue = [&](int ch, int st) {
        const uint32_t aU = s0 + (uint32_t)st * P_STAGE, bU = aU + 128 * 144;
        const int kb = ch * 64;
        #pragma unroll
        for (int i = 0; i < 4; i++) {
            int id = i * 256 + tid; int m = id >> 3, q = id & 7;
            cp16(aU + (uint32_t)(m * 144 + q * 16),
                 g_xh + (size_t)(row0 + m) * NH + kb + q * 8);
        }
        #pragma unroll
        for (int i = 0; i < 4; i++) {
            int id = i * 256 + tid; int m = id >> 3, q = id & 7;
            cp16(bU + (uint32_t)(m * 144 + q * 16),
                 g_wih + (size_t)(col0 + m) * NH + kb + q * 8);
        }
        CP_COMMIT();
    };

    float acc[2][8][4];
    #pragma unroll
    for (int a = 0; a < 2; a++)
        #pragma unroll
        for (int b = 0; b < 8; b++)
            #pragma unroll
            for (int c = 0; c < 4; c++) acc[a][b][c] = 0.f;

    issue(0, 0); issue(1, 1);
    for (int c = 0; c < 16; ++c) {
        if (c < 15) { CP_WAIT(1); } else { CP_WAIT(0); }
        __syncthreads();
        if (c + 2 < 16) issue(c + 2, (c + 2) % 3);
        const uint32_t aU = s0 + (uint32_t)(c % 3) * P_STAGE, bU = aU + 128 * 144;
        #pragma unroll
        for (int ks = 0; ks < 4; ks++) {
            const int ko = ks * 8;
            uint32_t afr[2][4], bfr[4][4];
            #pragma unroll
            for (int mi = 0; mi < 2; mi++)
                ldsm4(afr[mi][0], afr[mi][1], afr[mi][2], afr[mi][3],
                      aU + (uint32_t)(((wr + mi * 16 + lrow) * 36 + ko + lhiw) * 4));
            #pragma unroll
            for (int nb = 0; nb < 4; nb++)
                ldsm4(bfr[nb][0], bfr[nb][1], bfr[nb][2], bfr[nb][3],
                      bU + (uint32_t)(((wc + nb * 16 + bn_row) * 36 + ko + bn_wof) * 4));
            #pragma unroll
            for (int mi = 0; mi < 2; mi++)
                #pragma unroll
                for (int n8 = 0; n8 < 8; n8++)
                    mma16816(acc[mi][n8], afr[mi],
                             bfr[n8 >> 1][2 * (n8 & 1)], bfr[n8 >> 1][2 * (n8 & 1) + 1]);
        }
        __syncthreads();
    }
    #pragma unroll
    for (int mi = 0; mi < 2; mi++) {
        int r0 = row0 + wr + mi * 16 + g;
        #pragma unroll
        for (int n8 = 0; n8 < 8; n8++) {
            int col = col0 + wc + n8 * 8 + 2 * t;
            *(float2*)&g_g0[(size_t)r0 * NG + col]       = make_float2(acc[mi][n8][0], acc[mi][n8][1]);
            *(float2*)&g_g0[(size_t)(r0 + 8) * NG + col] = make_float2(acc[mi][n8][2], acc[mi][n8][3]);
        }
    }
}

// =============== recurrent kernel ==================================================
// SMEM: A ring 4 stages x [h0 64x144B | h1 64x144B] + resident B 32 chunks.
// R16: R14 cadence (sync per chunk) with a 4-stage ring, lookahead 3, CP_WAIT(2):
// producers always keep >=2 groups in flight, so load completion never gates
// the consumer sync. Grid barrier: arrive split from spin; G0 prefetch between.
#define A_ROWB    144
#define R_STAGE   (128 * A_ROWB)             // 18432 (h0 half + h1 half)
#define B_OFF     (4 * R_STAGE)              // 73728
#define B_CHUNK_B (32 * A_ROWB)              // 4608
#define SMEM_TOT  (B_OFF + 32 * B_CHUNK_B)   // 221184
#define NT 512

// 12 consumer warps: cg = wid>>2 (0: L0+=h0*Whh | 1: L1+=h0*Wih | 2: L1+=h1*Whh),
// band = wid&3 (16-row band), warp tile 16x32. 4 producer warps (12-15) do all
// cp.async. G0 added in epilogue from registers (prefetched a slot early).
__global__ __launch_bounds__(NT) void k_lstm(float* __restrict__ out, int wstates) {
    extern __shared__ char dyn[];

    const int tid  = threadIdx.x;
    const int lane = tid & 31;
    const int wid  = tid >> 5;
    const int j0   = blockIdx.x * 8;

    const uint32_t smem0 = smem_u32(dyn);
    const uint32_t bRes  = smem0 + B_OFF;

    // ---- resident B (once): chunk-major, 16 Wih chunks then 16 Whh chunks ----
    {
        if (tid < 256) {
            const int n = tid >> 3, q = tid & 7;
            const int grow = (n >> 3) * NH + j0 + (n & 7);
            for (int c = 0; c < 32; c++) {
                const __half* wb = (c < 16) ? g_wih : g_whh;
                const int kk = (c * 64) & (NH - 1);
                cp16(bRes + (uint32_t)(c * B_CHUNK_B + n * A_ROWB + q * 16),
                     wb + (size_t)grow * NH + kk + q * 8);
                CP_COMMIT();
            }
        }
        CP_WAIT(0);
        __syncthreads();
    }

    const int g = lane >> 2, t = lane & 3;
    const int lrow = lane & 15, lhiw = (lane >> 4) * 4;
    const int bn_row = ((lane >> 4) << 3) + (lane & 7);
    const int bn_wof = ((lane >> 3) & 1) * 4;
    const uint32_t bFragBase = bRes + (uint32_t)((bn_row * 36 + bn_wof) * 4);

    const bool isCons = (wid < 12);
    const int  cg     = wid >> 2;          // 0..2 (consumers)
    const int  band   = wid & 3;
    const int  ptid   = tid & 127;         // producer lane-id within 4 warps

    // ---- persistent per-thread epilogue state ----
    const int erow  = tid >> 2;            // 0..127
    const int ehalf = erow >> 6;
    const int eb    = erow & 63;
    const int ejb   = (tid & 3) * 2;
    float cv[2] = {0.f, 0.f};
    float bias_r[4][2];
    #pragma unroll
    for (int q = 0; q < 4; q++)
        #pragma unroll
        for (int u = 0; u < 2; u++)
            bias_r[q][u] = g_bias[q * NH + j0 + ejb + u];

    float2 rg0[4];
    auto fetch_g0 = [&](int tt) {
        if (ehalf == 0) {
            const size_t base = ((size_t)tt * NB + eb) * NG + j0 + ejb;
            #pragma unroll
            for (int q = 0; q < 4; q++) rg0[q] = *(const float2*)&g_g0[base + q * NH];
        }
    };
    fetch_g0(0);

    for (int s = 0; s <= SEQ; ++s) {
        const int rp = s & 1, wq = rp ^ 1;
        const __half* h0r = g_h0[rp];
        const __half* h1r = g_h1[rp];
        __half* h0w = g_h0[wq];
        __half* h1w = g_h1[wq];
        const bool doL0 = (s < SEQ);
        const bool doL1 = (s > 0);
        const int  t1   = s - 1;

        // ---- producer chunk loader: chunk j -> stage slot ----
        auto issue_chunk = [&](int j, int slot) {
            const uint32_t st = smem0 + (uint32_t)slot * R_STAGE;
            const int kb = j * 64;
            #pragma unroll
            for (int i = 0; i < 4; i++) {
                int id = i * 128 + ptid; int m = id >> 3, q = id & 7;
                cp16(st + (uint32_t)(m * A_ROWB + q * 16), h0r + m * NH + kb + q * 8);
            }
            #pragma unroll
            for (int i = 0; i < 4; i++) {
                int id = i * 128 + ptid; int m = id >> 3, q = id & 7;
                cp16(st + (uint32_t)(9216 + m * A_ROWB + q * 16), h1r + m * NH + kb + q * 8);
            }
            CP_COMMIT();
        };

        float acc[4][4];
        #pragma unroll
        for (int b = 0; b < 4; b++)
            #pragma unroll
            for (int c = 0; c < 4; c++) acc[b][c] = 0.f;

        // prologue: 3 chunks deep
        if (!isCons) { issue_chunk(0, 0); issue_chunk(1, 1); issue_chunk(2, 2); }

        for (int c = 0; c < 16; ++c) {
            if (!isCons) {
                if      (c <= 13) CP_WAIT(2);     // chunk c's group complete
                else if (c == 14) CP_WAIT(1);
                else              CP_WAIT(0);
            }
            __syncthreads();
            if (!isCons) {
                if (c + 3 < 16) issue_chunk(c + 3, (c + 3) & 3);
            } else {
                const uint32_t aBase = smem0 + (uint32_t)(c & 3) * R_STAGE
                                     + (cg == 2 ? 9216u : 0u);
                const uint32_t bC = bFragBase
                                  + (uint32_t)(((cg == 1) ? c : 16 + c) * B_CHUNK_B);
                #pragma unroll
                for (int ks = 0; ks < 4; ks++) {
                    const int ko = ks * 8;
                    uint32_t afr[4], b0[4], b1[4];
                    ldsm4(afr[0], afr[1], afr[2], afr[3],
                          aBase + (uint32_t)(((band * 16 + lrow) * 36 + ko + lhiw) * 4));
                    ldsm4(b0[0], b0[1], b0[2], b0[3], bC + (uint32_t)(ko * 4));
                    ldsm4(b1[0], b1[1], b1[2], b1[3], bC + (uint32_t)(16 * 144 + ko * 4));
                    mma16816(acc[0], afr, b0[0], b0[1]);
                    mma16816(acc[1], afr, b0[2], b0[3]);
                    mma16816(acc[2], afr, b1[0], b1[1]);
                    mma16816(acc[3], afr, b1[2], b1[3]);
                }
            }
        }

        __syncthreads();                  // mainloop done; ring free for sG

        // ------- gate exchange: sG0 [128][36] (rows 0-63 gemm0, 64-127 gemm1),
        //         sG2 [64][36] (gemm2, added to rows 64-127) -------
        float* sG0 = (float*)dyn;
        float* sG2 = (float*)(dyn + 18432);
        if (isCons) {
            float* dst = (cg == 0) ? sG0 : (cg == 1 ? sG0 + 64 * 36 : sG2);
            const int r = band * 16 + g;
            #pragma unroll
            for (int ni = 0; ni < 4; ni++) {
                int cc = ni * 8 + 2 * t;
                dst[r * 36 + cc]           = acc[ni][0];
                dst[r * 36 + cc + 1]       = acc[ni][1];
                dst[(r + 8) * 36 + cc]     = acc[ni][2];
                dst[(r + 8) * 36 + cc + 1] = acc[ni][3];
            }
        }
        __syncthreads();

        {
            const bool act = (ehalf == 0) ? doL0 : doL1;
            if (act) {
                __half* hwb = ehalf ? h1w : h0w;
                const int idx = eb * NH + j0 + ejb;
                float hv[2];
                #pragma unroll
                for (int u = 0; u < 2; u++) {
                    int uu = ejb + u;
                    float gq[4];
                    #pragma unroll
                    for (int q = 0; q < 4; q++) {
                        gq[q] = sG0[erow * 36 + q * 8 + uu] + bias_r[q][u];
                        if (ehalf == 0) gq[q] += (u == 0 ? rg0[q].x : rg0[q].y);
                        else            gq[q] += sG2[(erow - 64) * 36 + q * 8 + uu];
                    }
                    float cn = fsig(gq[1]) * cv[u] + fsig(gq[0]) * ftanh(gq[2]);
                    cv[u] = cn;
                    hv[u] = fsig(gq[3]) * ftanh(cn);
                }
                *(__half2*)&hwb[idx] = __floats2half2_rn(hv[0], hv[1]);
                if (ehalf == 1) {
                    *(float2*)&out[((size_t)t1 * NB + eb) * NH + j0 + ejb] =
                        make_float2(hv[0], hv[1]);
                    if (wstates && t1 == SEQ - 1) {
                        #pragma unroll
                        for (int u = 0; u < 2; u++) {
                            out[(size_t)SEQ * NB * NH + NB * NH + idx + u]     = hv[u];
                            out[(size_t)SEQ * NB * NH + 3 * NB * NH + idx + u] = cv[u];
                        }
                    }
                } else if (wstates && s == SEQ - 1) {
                    #pragma unroll
                    for (int u = 0; u < 2; u++) {
                        out[(size_t)SEQ * NB * NH + idx + u]               = hv[u];
                        out[(size_t)SEQ * NB * NH + 2 * NB * NH + idx + u] = cv[u];
                    }
                }
            }
        }

        // ------- grid barrier: arrive early, prefetch G0 under the wait -------
        if (s < SEQ) {
            __syncthreads();              // all h writes done block-wide
            unsigned arr = 0u;
            if (tid == 0) {
                __threadfence();
                arr = atomicAdd(&g_cnt, 1u);   // ARRIVE (no spin yet)
            }
            fetch_g0((s + 1 < SEQ) ? (s + 1) : (SEQ - 1));  // overlaps other arrivals
            if (tid == 0) {
                unsigned target = (unsigned)(s + 1);
                if (arr == 127u) {
                    g_cnt = 0u;
                    __threadfence();
                    g_gen = target;
                } else {
                    while (g_gen < target) { }
                    __threadfence();
                }
            }
            __syncthreads();
        }
    }
}

// ---------------------------------------------------------------------------------
extern "C" void kernel_launch(void* const* d_in, const int* in_sizes, int n_in,
                              void* d_out, int out_size) {
    const float* x   = (const float*)d_in[0];
    const float* wih = (const float*)d_in[1];
    const float* whh = (const float*)d_in[2];
    const float* bih = (const float*)d_in[3];
    const float* bhh = (const float*)d_in[4];
    float* out = (float*)d_out;

    const long long full = (long long)SEQ * NB * NH + 4LL * NB * NH;
    int wstates = ((long long)out_size >= full) ? 1 : 0;

    static int smem_set = 0;
    if (!smem_set) {
        cudaFuncSetAttribute(k_lstm, cudaFuncAttributeMaxDynamicSharedMemorySize, SMEM_TOT);
        cudaFuncSetAttribute(k_pre,  cudaFuncAttributeMaxDynamicSharedMemorySize, P_SMEM);
        smem_set = 1;
    }

    k_cvt<<<512, 256>>>(x, 0, SEQ * NB * NH / 4);
    k_cvt<<<256, 256>>>(wih, 1, NG * NH / 4);
    k_cvt<<<256, 256>>>(whh, 2, NG * NH / 4);
    k_bias<<<16, 256>>>(bih, bhh);
    k_init<<<128, 256>>>();

    k_pre<<<dim3(NG / 128, SEQ * NB / 128), 256, P_SMEM>>>();

    k_lstm<<<128, NT, SMEM_TOT>>>(out, wstates);
}